// round 5
// baseline (speedup 1.0000x reference)
#include <cuda_runtime.h>
#include <cstdint>
#include <cstddef>

#define HD 1024
#define BA 64
#define TS 256
#define NL 4
#define MR (BA*TS)
#define NCTA 128
#define WP 34        // Ws pitch (floats): conflict-free + 8B-aligned pairs

// ---------------- device scratch ----------------
__device__ float    g_A[(size_t)MR * HD];
__device__ float    g_X[(size_t)MR * HD];
__device__ float    g_hT2[2][HD * BA];      // h transposed, double-buffered: [par][k][b]
__device__ float2   g_sb[2][32 * BA];       // partial LN stats, double-buffered
__device__ unsigned g_stag[NCTA];           // stats tags (per writer CTA)
__device__ unsigned g_htag[NCTA];           // h tags (per writer CTA)
__device__ unsigned g_bar;                  // one-shot prologue barrier

typedef unsigned long long ull;

__device__ __forceinline__ void fma2(ull& d, ull a, ull b) {
    asm volatile("fma.rn.f32x2 %0, %1, %2, %0;" : "+l"(d) : "l"(a), "l"(b));
}
__device__ __forceinline__ void add2(ull& d, ull a) {
    asm volatile("add.rn.f32x2 %0, %0, %1;" : "+l"(d) : "l"(a));
}
__device__ __forceinline__ ull splat(float x) {
    ull d; asm("mov.b64 %0, {%1, %1};" : "=l"(d) : "f"(x)); return d;
}
__device__ __forceinline__ float2 unpk(ull v) {
    float2 r; asm("mov.b64 {%0, %1}, %2;" : "=f"(r.x), "=f"(r.y) : "l"(v)); return r;
}
__device__ __forceinline__ unsigned ldacq(const unsigned* p) {
    unsigned v; asm volatile("ld.acquire.gpu.u32 %0, [%1];" : "=r"(v) : "l"(p)); return v;
}
__device__ __forceinline__ void strel(unsigned* p, unsigned v) {
    asm volatile("st.release.gpu.u32 [%0], %1;" :: "l"(p), "r"(v));
}
__device__ __forceinline__ void redrel(unsigned* p) {
    asm volatile("red.release.gpu.global.add.u32 [%0], 1;" :: "l"(p));
}
__device__ __forceinline__ void cpa16(void* dst, const void* src) {
    uint32_t d = (uint32_t)__cvta_generic_to_shared(dst);
    asm volatile("cp.async.cg.shared.global [%0], [%1], 16;" :: "r"(d), "l"(src));
}

// =====================================================================
// GEMM (unchanged): out = X @ W^T + bias;  M=16384, N=K=1024
// =====================================================================
__global__ __launch_bounds__(256, 2) void gemm_f2(
    const float* __restrict__ X, const float* __restrict__ W,
    const float* __restrict__ bias, float* __restrict__ out)
{
    __shared__ float sA[2][8][128];
    __shared__ float sB[2][8][128];
    const int tid = threadIdx.x;
    const int r = tid >> 1, hf = tid & 1;
    const int ty = tid >> 4, tx = tid & 15;

    const float* xp = X + (size_t)(blockIdx.y * 128 + r) * HD + hf * 4;
    const float* wp = W + (size_t)(blockIdx.x * 128 + r) * HD + hf * 4;

    ull acc[8][4];
    #pragma unroll
    for (int i = 0; i < 8; i++)
        #pragma unroll
        for (int j = 0; j < 4; j++) acc[i][j] = 0ull;

    float4 xa = *(const float4*)xp;
    float4 wa = *(const float4*)wp;
    {
        int kb = hf * 4;
        sA[0][kb+0][r] = xa.x; sA[0][kb+1][r] = xa.y; sA[0][kb+2][r] = xa.z; sA[0][kb+3][r] = xa.w;
        sB[0][kb+0][r] = wa.x; sB[0][kb+1][r] = wa.y; sB[0][kb+2][r] = wa.z; sB[0][kb+3][r] = wa.w;
    }
    __syncthreads();

    for (int c = 0; c < 128; c++) {
        const int cur = c & 1;
        if (c < 127) {
            xa = *(const float4*)(xp + (size_t)(c + 1) * 8);
            wa = *(const float4*)(wp + (size_t)(c + 1) * 8);
        }
        #pragma unroll
        for (int k = 0; k < 8; k++) {
            float4 a0 = *(const float4*)&sA[cur][k][ty * 8];
            float4 a1 = *(const float4*)&sA[cur][k][ty * 8 + 4];
            ulonglong2 b0 = *(const ulonglong2*)&sB[cur][k][tx * 8];
            ulonglong2 b1 = *(const ulonglong2*)&sB[cur][k][tx * 8 + 4];
            ull as[8] = { splat(a0.x), splat(a0.y), splat(a0.z), splat(a0.w),
                          splat(a1.x), splat(a1.y), splat(a1.z), splat(a1.w) };
            #pragma unroll
            for (int i = 0; i < 8; i++) {
                fma2(acc[i][0], as[i], b0.x);
                fma2(acc[i][1], as[i], b0.y);
                fma2(acc[i][2], as[i], b1.x);
                fma2(acc[i][3], as[i], b1.y);
            }
        }
        if (c < 127) {
            int kb = hf * 4, nb = cur ^ 1;
            sA[nb][kb+0][r] = xa.x; sA[nb][kb+1][r] = xa.y; sA[nb][kb+2][r] = xa.z; sA[nb][kb+3][r] = xa.w;
            sB[nb][kb+0][r] = wa.x; sB[nb][kb+1][r] = wa.y; sB[nb][kb+2][r] = wa.z; sB[nb][kb+3][r] = wa.w;
        }
        __syncthreads();
    }

    const size_t m0 = (size_t)blockIdx.y * 128 + ty * 8;
    const int n0 = blockIdx.x * 128 + tx * 8;
    float bl[8];
    #pragma unroll
    for (int j = 0; j < 8; j++) bl[j] = __ldg(bias + n0 + j);
    #pragma unroll
    for (int i = 0; i < 8; i++) {
        float2 p0 = unpk(acc[i][0]), p1 = unpk(acc[i][1]);
        float2 p2 = unpk(acc[i][2]), p3 = unpk(acc[i][3]);
        float4 o0 = make_float4(p0.x + bl[0], p0.y + bl[1], p1.x + bl[2], p1.y + bl[3]);
        float4 o1 = make_float4(p2.x + bl[4], p2.y + bl[5], p3.x + bl[6], p3.y + bl[7]);
        *(float4*)&out[(m0 + i) * HD + n0]     = o0;
        *(float4*)&out[(m0 + i) * HD + n0 + 4] = o1;
    }
}

// =====================================================================
// Recurrence with dataflow tags. 128 CTAs = 4 batch-groups x 32 f-groups.
// CTA (bg,ng): 16 batch rows x 32 features. Warp w: K-chunk [128w,128w+128)
// produced by CTAs {(bg<<5)|ng', ng' in [4w,4w+4)} -> warp-local tag gate.
// =====================================================================
__global__ void rst_tags() {
    int i = threadIdx.x;
    if (i < NCTA) { g_stag[i] = 0u; g_htag[i] = 0u; }
    if (i == 0) g_bar = 0u;
}

#define SMEM_DYN ((HD*WP + HD*16) * 4 + 8*16*17*8)

__global__ __launch_bounds__(256, 1) void recur(
    const float* __restrict__ A, const float* __restrict__ Wh,
    const float* __restrict__ lng, const float* __restrict__ lnb,
    float* __restrict__ xout)
{
    extern __shared__ char dsm[];
    float* Ws = (float*)dsm;                              // [1024][WP]
    float* Hs = (float*)(dsm + (size_t)HD*WP*4);          // [1024][16]
    ull*   red = (ull*)(dsm + (size_t)(HD*WP + HD*16)*4); // [8][16][17]
    __shared__ float s_mu[16], s_rs[16], s_g[32], s_b[32];

    const int tid = threadIdx.x, cta = blockIdx.x;
    const int bg = cta >> 5, ng = cta & 31;
    const int B0 = bg * 16, n0 = ng * 32;
    const int w = tid >> 5, lane = tid & 31;
    const int fh = lane & 15, bo = lane >> 4;
    const int b_i = tid >> 4, fp = tid & 15;

    // prologue: Ws[k][f] = Wh[n0+f][k]
    for (int i = tid; i < 32 * HD; i += 256) {
        int k = i & 1023, f = i >> 10;
        Ws[k * WP + f] = Wh[(size_t)(n0 + f) * HD + k];
    }
    if (tid < 32) { s_g[tid] = lng[n0 + tid]; s_b[tid] = lnb[n0 + tid]; }
    // zero our block of h buffer 0
    if (tid < 128) {
        int rr = tid >> 2, q = tid & 3;
        __stcg((float4*)&g_hT2[0][(n0 + rr) * BA + B0 + q * 4], make_float4(0.f,0.f,0.f,0.f));
    }
    __syncthreads();

    // one-shot global barrier: h0 zeroed + everyone resident
    if (tid == 0) {
        redrel(&g_bar);
        while (ldacq(&g_bar) < NCTA) { }
    }
    __syncthreads();

    const int k0 = w * 128;
    float* HsW = Hs + k0 * 16;

    for (int t = 0; t < TS; t++) {
        // A prefetch (independent of gates)
        float2 aA = __ldcg((const float2*)&A[((size_t)(B0 + b_i) * TS + t) * HD + n0 + fp * 2]);

        // warp-local gate on our 4 h producers, then cp.async our chunk
        if (t > 0) {
            if (lane < 4) {
                const unsigned* tp = &g_htag[(bg << 5) | (4 * w + lane)];
                while (ldacq(tp) < (unsigned)t) { }
            }
            __syncwarp();
        }
        {
            const float* srcb = g_hT2[t & 1] + (size_t)k0 * BA + B0;
            #pragma unroll
            for (int j = 0; j < 8; j++) {
                int lin = j * 32 + lane, kl = lin >> 2, q = lin & 3;
                cpa16(HsW + kl * 16 + q * 4, srcb + (size_t)kl * BA + q * 4);
            }
            asm volatile("cp.async.commit_group;");
            #pragma unroll
            for (int j = 8; j < 16; j++) {
                int lin = j * 32 + lane, kl = lin >> 2, q = lin & 3;
                cpa16(HsW + kl * 16 + q * 4, srcb + (size_t)kl * BA + q * 4);
            }
            asm volatile("cp.async.commit_group;");
        }

        ull acc[8];
        #pragma unroll
        for (int j = 0; j < 8; j++) acc[j] = 0ull;

        asm volatile("cp.async.wait_group 1;");
        #pragma unroll 8
        for (int k = k0; k < k0 + 64; k++) {
            ull w2 = *(const ull*)(Ws + (size_t)k * WP + fh * 2);
            float4 h0 = *(const float4*)(Hs + k * 16 + bo * 8);
            float4 h1 = *(const float4*)(Hs + k * 16 + bo * 8 + 4);
            fma2(acc[0], splat(h0.x), w2); fma2(acc[1], splat(h0.y), w2);
            fma2(acc[2], splat(h0.z), w2); fma2(acc[3], splat(h0.w), w2);
            fma2(acc[4], splat(h1.x), w2); fma2(acc[5], splat(h1.y), w2);
            fma2(acc[6], splat(h1.z), w2); fma2(acc[7], splat(h1.w), w2);
        }
        asm volatile("cp.async.wait_group 0;");
        #pragma unroll 8
        for (int k = k0 + 64; k < k0 + 128; k++) {
            ull w2 = *(const ull*)(Ws + (size_t)k * WP + fh * 2);
            float4 h0 = *(const float4*)(Hs + k * 16 + bo * 8);
            float4 h1 = *(const float4*)(Hs + k * 16 + bo * 8 + 4);
            fma2(acc[0], splat(h0.x), w2); fma2(acc[1], splat(h0.y), w2);
            fma2(acc[2], splat(h0.z), w2); fma2(acc[3], splat(h0.w), w2);
            fma2(acc[4], splat(h1.x), w2); fma2(acc[5], splat(h1.y), w2);
            fma2(acc[6], splat(h1.z), w2); fma2(acc[7], splat(h1.w), w2);
        }

        #pragma unroll
        for (int j = 0; j < 8; j++)
            red[(w * 16 + bo * 8 + j) * 17 + fh] = acc[j];
        __syncthreads();

        // K-reduce across 8 warps
        ull z = red[(0 * 16 + b_i) * 17 + fp];
        #pragma unroll
        for (int ww = 1; ww < 8; ww++) add2(z, red[(ww * 16 + b_i) * 17 + fp]);
        float2 z2 = unpk(z);
        z2.x += aA.x; z2.y += aA.y;

        // partial LN stats over our 32 features
        float s = z2.x + z2.y;
        float q = z2.x * z2.x + z2.y * z2.y;
        s += __shfl_xor_sync(0xffffffffu, s, 1); q += __shfl_xor_sync(0xffffffffu, q, 1);
        s += __shfl_xor_sync(0xffffffffu, s, 2); q += __shfl_xor_sync(0xffffffffu, q, 2);
        s += __shfl_xor_sync(0xffffffffu, s, 4); q += __shfl_xor_sync(0xffffffffu, q, 4);
        s += __shfl_xor_sync(0xffffffffu, s, 8); q += __shfl_xor_sync(0xffffffffu, q, 8);
        if (fp == 0) __stcg((float2*)&g_sb[t & 1][ng * BA + B0 + b_i], make_float2(s, q));
        __syncthreads();
        if (tid == 0) {
            __threadfence();
            strel(&g_stag[cta], (unsigned)(t + 1));
        }

        // gate on 32 same-bg stats producers (32 threads, 1 tag each)
        if (tid < 32) {
            const unsigned* tp = &g_stag[(bg << 5) | tid];
            while (ldacq(tp) < (unsigned)(t + 1)) { }
        }
        __syncthreads();

        if (tid < 64) {
            int rr = tid >> 2, c = tid & 3;
            float ss = 0.f, qq = 0.f;
            #pragma unroll
            for (int m = 0; m < 8; m++) {
                float2 v = __ldcg((const float2*)&g_sb[t & 1][(c * 8 + m) * BA + B0 + rr]);
                ss += v.x; qq += v.y;
            }
            ss += __shfl_xor_sync(0xffffffffu, ss, 1); qq += __shfl_xor_sync(0xffffffffu, qq, 1);
            ss += __shfl_xor_sync(0xffffffffu, ss, 2); qq += __shfl_xor_sync(0xffffffffu, qq, 2);
            if (c == 0) {
                float mu = ss * (1.f / HD);
                float var = qq * (1.f / HD) - mu * mu;
                s_mu[rr] = mu;
                s_rs[rr] = rsqrtf(var + 1e-5f);
            }
        }
        __syncthreads();

        const float mu = s_mu[b_i], rs = s_rs[b_i];
        const int f = fp * 2;
        float h0 = tanhf((z2.x - mu) * rs * s_g[f]     + s_b[f]);
        float h1 = tanhf((z2.y - mu) * rs * s_g[f + 1] + s_b[f + 1]);
        *(float2*)&xout[((size_t)(B0 + b_i) * TS + t) * HD + n0 + f] = make_float2(h0, h1);
        float* hb = g_hT2[(t + 1) & 1];
        __stcg(&hb[(n0 + f) * BA + B0 + b_i], h0);
        __stcg(&hb[(n0 + f + 1) * BA + B0 + b_i], h1);
        __syncthreads();
        if (tid == 0) {
            __threadfence();
            strel(&g_htag[cta], (unsigned)(t + 1));
        }
    }
}

// =====================================================================
extern "C" void kernel_launch(void* const* d_in, const int* in_sizes, int n_in,
                              void* d_out, int out_size)
{
    const float* inputs = (const float*)d_in[0];
    const float* Wx     = (const float*)d_in[1];
    const float* bx     = (const float*)d_in[2];
    const float* Wh     = (const float*)d_in[3];
    const float* lng    = (const float*)d_in[4];
    const float* lnb    = (const float*)d_in[5];
    const float* Wy     = (const float*)d_in[6];
    const float* by     = (const float*)d_in[7];

    float* out_x = (float*)d_out;
    float* out_y = out_x + (size_t)MR * HD;

    float* pA = nullptr; float* pX = nullptr;
    cudaGetSymbolAddress((void**)&pA, g_A);
    cudaGetSymbolAddress((void**)&pX, g_X);

    cudaFuncSetAttribute(recur, cudaFuncAttributeMaxDynamicSharedMemorySize, SMEM_DYN);

    dim3 ggrid(8, 128);
    const float* xin = inputs;
    for (int l = 0; l < NL; l++) {
        gemm_f2<<<ggrid, 256>>>(xin, Wx + (size_t)l * HD * HD, bx + (size_t)l * HD, pA);
        rst_tags<<<1, 128>>>();
        float* xo = (l == NL - 1) ? out_x : pX;
        recur<<<NCTA, 256, SMEM_DYN>>>(pA, Wh + (size_t)l * HD * HD,
                                       lng + (size_t)l * HD, lnb + (size_t)l * HD, xo);
        xin = xo;
    }
    gemm_f2<<<ggrid, 256>>>(out_x, Wy, by, out_y);
}

// round 6
// speedup vs baseline: 2.2654x; 2.2654x over previous
#include <cuda_runtime.h>
#include <cstdint>
#include <cstddef>

#define HD 1024
#define BA 64
#define TS 256
#define NL 4
#define MR (BA*TS)
#define NCTA 128
#define WP 34        // recur Ws pitch (floats)
#define GP 24        // gemm smem pitch (bf16 units, 48B: conflict-free, 16B-aligned)

// ---------------- device scratch ----------------
__device__ float    g_A[(size_t)MR * HD];
__device__ float    g_X[(size_t)MR * HD];
__device__ float    g_hT[HD * BA];          // h transposed: [k][b]
__device__ float2   g_st2[32 * BA];         // [ng][b] partial stats
__device__ unsigned g_bar;
__device__ uint16_t g_Xh[(size_t)MR * HD];  // X hi plane (bf16)
__device__ uint16_t g_Xl[(size_t)MR * HD];  // X lo plane
__device__ uint16_t g_Wph[(size_t)HD * HD]; // W hi plane
__device__ uint16_t g_Wpl[(size_t)HD * HD]; // W lo plane

typedef unsigned long long ull;

__device__ __forceinline__ void fma2(ull& d, ull a, ull b) {
    asm volatile("fma.rn.f32x2 %0, %1, %2, %0;" : "+l"(d) : "l"(a), "l"(b));
}
__device__ __forceinline__ void add2(ull& d, ull a) {
    asm volatile("add.rn.f32x2 %0, %0, %1;" : "+l"(d) : "l"(a));
}
__device__ __forceinline__ ull splat(float x) {
    ull d; asm("mov.b64 %0, {%1, %1};" : "=l"(d) : "f"(x)); return d;
}
__device__ __forceinline__ float2 unpk(ull v) {
    float2 r; asm("mov.b64 {%0, %1}, %2;" : "=f"(r.x), "=f"(r.y) : "l"(v)); return r;
}
__device__ __forceinline__ unsigned ldacq(const unsigned* p) {
    unsigned v; asm volatile("ld.acquire.gpu.u32 %0, [%1];" : "=r"(v) : "l"(p)); return v;
}
__device__ __forceinline__ void redrel(unsigned* p) {
    asm volatile("red.release.gpu.global.add.u32 [%0], 1;" :: "l"(p));
}
__device__ __forceinline__ void cpa16(void* dst, const void* src) {
    uint32_t d = (uint32_t)__cvta_generic_to_shared(dst);
    asm volatile("cp.async.cg.shared.global [%0], [%1], 16;" :: "r"(d), "l"(src));
}
__device__ __forceinline__ uint16_t bf16_bits(float x) {
    uint32_t u = __float_as_uint(x);
    return (uint16_t)((u + 0x7fffu + ((u >> 16) & 1u)) >> 16);
}
__device__ __forceinline__ float bf16f(uint16_t b) {
    return __uint_as_float(((uint32_t)b) << 16);
}
__device__ __forceinline__ void mma_bf16(float c[4], const uint32_t a[4], const uint32_t b[2]) {
    asm volatile(
        "mma.sync.aligned.m16n8k16.row.col.f32.bf16.bf16.f32 "
        "{%0,%1,%2,%3}, {%4,%5,%6,%7}, {%8,%9}, {%0,%1,%2,%3};"
        : "+f"(c[0]), "+f"(c[1]), "+f"(c[2]), "+f"(c[3])
        : "r"(a[0]), "r"(a[1]), "r"(a[2]), "r"(a[3]), "r"(b[0]), "r"(b[1]));
}

// =====================================================================
// fp32 -> (hi, lo) bf16 planes
// =====================================================================
__global__ void conv_split(const float* __restrict__ src,
                           uint16_t* __restrict__ hi, uint16_t* __restrict__ lo, int n4)
{
    for (int i = blockIdx.x * blockDim.x + threadIdx.x; i < n4; i += gridDim.x * blockDim.x) {
        float4 v = __ldcg((const float4*)src + i);
        uint16_t h0 = bf16_bits(v.x), h1 = bf16_bits(v.y);
        uint16_t h2 = bf16_bits(v.z), h3 = bf16_bits(v.w);
        uint16_t l0 = bf16_bits(v.x - bf16f(h0)), l1 = bf16_bits(v.y - bf16f(h1));
        uint16_t l2 = bf16_bits(v.z - bf16f(h2)), l3 = bf16_bits(v.w - bf16f(h3));
        ull hp = (ull)h0 | ((ull)h1 << 16) | ((ull)h2 << 32) | ((ull)h3 << 48);
        ull lp = (ull)l0 | ((ull)l1 << 16) | ((ull)l2 << 32) | ((ull)l3 << 48);
        ((ull*)hi)[i] = hp;
        ((ull*)lo)[i] = lp;
    }
}

// =====================================================================
// Tensor-core split-bf16 GEMM: out = X @ W^T + bias;  M=16384, N=K=1024
// 128x128 tile, 256 thr (4x2 warps), cp.async double-buffered, K-chunk 16
// =====================================================================
__global__ __launch_bounds__(256, 2) void gemm_tc(
    const uint16_t* __restrict__ Xh, const uint16_t* __restrict__ Xl,
    const uint16_t* __restrict__ Wh, const uint16_t* __restrict__ Wl,
    const float* __restrict__ bias, float* __restrict__ out)
{
    __shared__ uint16_t sm[2][4][128 * GP];   // planes: 0=Xh 1=Xl 2=Wh 3=Wl

    const int tid = threadIdx.x;
    const int bn = blockIdx.x, bm = blockIdx.y;
    const int warp = tid >> 5, lane = tid & 31;
    const int g = lane >> 2, tq = lane & 3;
    const int wm = warp >> 1, wn = warp & 1;

    // loader mapping: 4 transfers/thread
    const uint16_t* gsrc[4];
    int pl[4], dof[4];
    #pragma unroll
    for (int j = 0; j < 4; j++) {
        int lin = j * 256 + tid;
        int plane = lin >> 8, rem = lin & 255;
        int row = rem >> 1, half = rem & 1;
        pl[j] = plane; dof[j] = row * GP + half * 8;
        const uint16_t* base;
        if      (plane == 0) base = Xh + (size_t)(bm * 128 + row) * HD;
        else if (plane == 1) base = Xl + (size_t)(bm * 128 + row) * HD;
        else if (plane == 2) base = Wh + (size_t)(bn * 128 + row) * HD;
        else                 base = Wl + (size_t)(bn * 128 + row) * HD;
        gsrc[j] = base + half * 8;
    }
    auto issue = [&](int buf, int c) {
        int k0 = c * 16;
        #pragma unroll
        for (int j = 0; j < 4; j++) cpa16(&sm[buf][pl[j]][dof[j]], gsrc[j] + k0);
        asm volatile("cp.async.commit_group;");
    };

    float acc[2][8][4];
    #pragma unroll
    for (int mt = 0; mt < 2; mt++)
        #pragma unroll
        for (int nt = 0; nt < 8; nt++)
            #pragma unroll
            for (int j = 0; j < 4; j++) acc[mt][nt][j] = 0.f;

    issue(0, 0);
    const int NCH = HD / 16;   // 64
    for (int c = 0; c < NCH; c++) {
        const int cur = c & 1;
        if (c + 1 < NCH) {
            issue(cur ^ 1, c + 1);
            asm volatile("cp.async.wait_group 1;");
        } else {
            asm volatile("cp.async.wait_group 0;");
        }
        __syncthreads();

        uint32_t aH[2][4], aL[2][4];
        #pragma unroll
        for (int mt = 0; mt < 2; mt++) {
            int row = wm * 32 + mt * 16 + g;
            aH[mt][0] = *(const uint32_t*)&sm[cur][0][row * GP + 2 * tq];
            aH[mt][1] = *(const uint32_t*)&sm[cur][0][(row + 8) * GP + 2 * tq];
            aH[mt][2] = *(const uint32_t*)&sm[cur][0][row * GP + 8 + 2 * tq];
            aH[mt][3] = *(const uint32_t*)&sm[cur][0][(row + 8) * GP + 8 + 2 * tq];
            aL[mt][0] = *(const uint32_t*)&sm[cur][1][row * GP + 2 * tq];
            aL[mt][1] = *(const uint32_t*)&sm[cur][1][(row + 8) * GP + 2 * tq];
            aL[mt][2] = *(const uint32_t*)&sm[cur][1][row * GP + 8 + 2 * tq];
            aL[mt][3] = *(const uint32_t*)&sm[cur][1][(row + 8) * GP + 8 + 2 * tq];
        }
        #pragma unroll
        for (int nt = 0; nt < 8; nt++) {
            int n = wn * 64 + nt * 8 + g;
            uint32_t bH[2], bL[2];
            bH[0] = *(const uint32_t*)&sm[cur][2][n * GP + 2 * tq];
            bH[1] = *(const uint32_t*)&sm[cur][2][n * GP + 8 + 2 * tq];
            bL[0] = *(const uint32_t*)&sm[cur][3][n * GP + 2 * tq];
            bL[1] = *(const uint32_t*)&sm[cur][3][n * GP + 8 + 2 * tq];
            #pragma unroll
            for (int mt = 0; mt < 2; mt++) {
                mma_bf16(acc[mt][nt], aH[mt], bH);
                mma_bf16(acc[mt][nt], aH[mt], bL);
                mma_bf16(acc[mt][nt], aL[mt], bH);
            }
        }
        __syncthreads();
    }

    #pragma unroll
    for (int mt = 0; mt < 2; mt++) {
        int row = bm * 128 + wm * 32 + mt * 16 + g;
        #pragma unroll
        for (int nt = 0; nt < 8; nt++) {
            int col = bn * 128 + wn * 64 + nt * 8 + 2 * tq;
            float b0 = __ldg(bias + col), b1 = __ldg(bias + col + 1);
            *(float2*)&out[(size_t)row * HD + col] =
                make_float2(acc[mt][nt][0] + b0, acc[mt][nt][1] + b1);
            *(float2*)&out[(size_t)(row + 8) * HD + col] =
                make_float2(acc[mt][nt][2] + b0, acc[mt][nt][3] + b1);
        }
    }
}

// =====================================================================
// Recurrence (R4, validated): 128 CTAs = 4 bg x 32 ng, central barrier
// =====================================================================
__global__ void rst_bar() { g_bar = 0u; }

#define SMEM_DYN ((HD*WP + HD*16) * 4 + 8*16*17*8)

__global__ __launch_bounds__(256, 1) void recur(
    const float* __restrict__ A, const float* __restrict__ Wh,
    const float* __restrict__ lng, const float* __restrict__ lnb,
    float* __restrict__ xout)
{
    extern __shared__ char dsm[];
    float* Ws = (float*)dsm;                              // [1024][WP]
    float* Hs = (float*)(dsm + (size_t)HD*WP*4);          // [1024][16]
    ull*   red = (ull*)(dsm + (size_t)(HD*WP + HD*16)*4); // [8][16][17]
    __shared__ float s_mu[16], s_rs[16], s_g[32], s_b[32];

    const int tid = threadIdx.x, cta = blockIdx.x;
    const int bg = cta >> 5, ng = cta & 31;
    const int B0 = bg * 16, n0 = ng * 32;
    const int w = tid >> 5, lane = tid & 31;
    const int fh = lane & 15, bo = lane >> 4;
    const int b_i = tid >> 4, fp = tid & 15;

    for (int i = tid; i < 32 * HD; i += 256) {
        int k = i & 1023, f = i >> 10;
        Ws[k * WP + f] = Wh[(size_t)(n0 + f) * HD + k];
    }
    if (tid < 32) { s_g[tid] = lng[n0 + tid]; s_b[tid] = lnb[n0 + tid]; }
    if (tid < 128) {
        int rr = tid >> 2, q = tid & 3;
        __stcg((float4*)&g_hT[(n0 + rr) * BA + B0 + q * 4], make_float4(0.f,0.f,0.f,0.f));
    }
    __syncthreads();

    unsigned tgt = 0;
    auto gbar = [&]() {
        __syncthreads();
        tgt += NCTA;
        if (tid == 0) {
            redrel(&g_bar);
            while (ldacq(&g_bar) < tgt) { }
        }
        __syncthreads();
    };
    gbar();

    const int k0 = w * 128;
    float* HsW = Hs + k0 * 16;

    for (int t = 0; t < TS; t++) {
        float2 aA = __ldcg((const float2*)&A[((size_t)(B0 + b_i) * TS + t) * HD + n0 + fp * 2]);

        {
            const float* srcb = g_hT + (size_t)k0 * BA + B0;
            #pragma unroll
            for (int j = 0; j < 8; j++) {
                int lin = j * 32 + lane, kl = lin >> 2, q = lin & 3;
                cpa16(HsW + kl * 16 + q * 4, srcb + (size_t)kl * BA + q * 4);
            }
            asm volatile("cp.async.commit_group;");
            #pragma unroll
            for (int j = 8; j < 16; j++) {
                int lin = j * 32 + lane, kl = lin >> 2, q = lin & 3;
                cpa16(HsW + kl * 16 + q * 4, srcb + (size_t)kl * BA + q * 4);
            }
            asm volatile("cp.async.commit_group;");
        }

        ull acc[8];
        #pragma unroll
        for (int j = 0; j < 8; j++) acc[j] = 0ull;

        asm volatile("cp.async.wait_group 1;");
        #pragma unroll 8
        for (int k = k0; k < k0 + 64; k++) {
            ull w2 = *(const ull*)(Ws + (size_t)k * WP + fh * 2);
            float4 h0 = *(const float4*)(Hs + k * 16 + bo * 8);
            float4 h1 = *(const float4*)(Hs + k * 16 + bo * 8 + 4);
            fma2(acc[0], splat(h0.x), w2); fma2(acc[1], splat(h0.y), w2);
            fma2(acc[2], splat(h0.z), w2); fma2(acc[3], splat(h0.w), w2);
            fma2(acc[4], splat(h1.x), w2); fma2(acc[5], splat(h1.y), w2);
            fma2(acc[6], splat(h1.z), w2); fma2(acc[7], splat(h1.w), w2);
        }
        asm volatile("cp.async.wait_group 0;");
        #pragma unroll 8
        for (int k = k0 + 64; k < k0 + 128; k++) {
            ull w2 = *(const ull*)(Ws + (size_t)k * WP + fh * 2);
            float4 h0 = *(const float4*)(Hs + k * 16 + bo * 8);
            float4 h1 = *(const float4*)(Hs + k * 16 + bo * 8 + 4);
            fma2(acc[0], splat(h0.x), w2); fma2(acc[1], splat(h0.y), w2);
            fma2(acc[2], splat(h0.z), w2); fma2(acc[3], splat(h0.w), w2);
            fma2(acc[4], splat(h1.x), w2); fma2(acc[5], splat(h1.y), w2);
            fma2(acc[6], splat(h1.z), w2); fma2(acc[7], splat(h1.w), w2);
        }

        #pragma unroll
        for (int j = 0; j < 8; j++)
            red[(w * 16 + bo * 8 + j) * 17 + fh] = acc[j];
        __syncthreads();

        ull z = red[(0 * 16 + b_i) * 17 + fp];
        #pragma unroll
        for (int ww = 1; ww < 8; ww++) add2(z, red[(ww * 16 + b_i) * 17 + fp]);
        float2 z2 = unpk(z);
        z2.x += aA.x; z2.y += aA.y;

        float s = z2.x + z2.y;
        float q = z2.x * z2.x + z2.y * z2.y;
        s += __shfl_xor_sync(0xffffffffu, s, 1); q += __shfl_xor_sync(0xffffffffu, q, 1);
        s += __shfl_xor_sync(0xffffffffu, s, 2); q += __shfl_xor_sync(0xffffffffu, q, 2);
        s += __shfl_xor_sync(0xffffffffu, s, 4); q += __shfl_xor_sync(0xffffffffu, q, 4);
        s += __shfl_xor_sync(0xffffffffu, s, 8); q += __shfl_xor_sync(0xffffffffu, q, 8);
        if (fp == 0) __stcg((float2*)&g_st2[ng * BA + B0 + b_i], make_float2(s, q));
        gbar();

        if (tid < 64) {
            int rr = tid >> 2, c = tid & 3;
            float ss = 0.f, qq = 0.f;
            #pragma unroll
            for (int m = 0; m < 8; m++) {
                float2 v = __ldcg((const float2*)&g_st2[(c * 8 + m) * BA + B0 + rr]);
                ss += v.x; qq += v.y;
            }
            ss += __shfl_xor_sync(0xffffffffu, ss, 1); qq += __shfl_xor_sync(0xffffffffu, qq, 1);
            ss += __shfl_xor_sync(0xffffffffu, ss, 2); qq += __shfl_xor_sync(0xffffffffu, qq, 2);
            if (c == 0) {
                float mu = ss * (1.f / HD);
                float var = qq * (1.f / HD) - mu * mu;
                s_mu[rr] = mu;
                s_rs[rr] = rsqrtf(var + 1e-5f);
            }
        }
        __syncthreads();

        const float mu = s_mu[b_i], rs = s_rs[b_i];
        const int f = fp * 2;
        float h0 = tanhf((z2.x - mu) * rs * s_g[f]     + s_b[f]);
        float h1 = tanhf((z2.y - mu) * rs * s_g[f + 1] + s_b[f + 1]);
        *(float2*)&xout[((size_t)(B0 + b_i) * TS + t) * HD + n0 + f] = make_float2(h0, h1);
        __stcg(&g_hT[(n0 + f) * BA + B0 + b_i], h0);
        __stcg(&g_hT[(n0 + f + 1) * BA + B0 + b_i], h1);
        gbar();
    }
}

// =====================================================================
extern "C" void kernel_launch(void* const* d_in, const int* in_sizes, int n_in,
                              void* d_out, int out_size)
{
    const float* inputs = (const float*)d_in[0];
    const float* Wx     = (const float*)d_in[1];
    const float* bx     = (const float*)d_in[2];
    const float* Wh     = (const float*)d_in[3];
    const float* lng    = (const float*)d_in[4];
    const float* lnb    = (const float*)d_in[5];
    const float* Wy     = (const float*)d_in[6];
    const float* by     = (const float*)d_in[7];

    float* out_x = (float*)d_out;
    float* out_y = out_x + (size_t)MR * HD;

    float* pA = nullptr; float* pX = nullptr;
    uint16_t *pXh, *pXl, *pWh, *pWl;
    cudaGetSymbolAddress((void**)&pA, g_A);
    cudaGetSymbolAddress((void**)&pX, g_X);
    cudaGetSymbolAddress((void**)&pXh, g_Xh);
    cudaGetSymbolAddress((void**)&pXl, g_Xl);
    cudaGetSymbolAddress((void**)&pWh, g_Wph);
    cudaGetSymbolAddress((void**)&pWl, g_Wpl);

    cudaFuncSetAttribute(recur, cudaFuncAttributeMaxDynamicSharedMemorySize, SMEM_DYN);

    dim3 ggrid(8, 128);
    const int NX4 = MR * HD / 4, NW4 = HD * HD / 4;
    const float* xin = inputs;
    for (int l = 0; l < NL; l++) {
        conv_split<<<512, 256>>>(Wx + (size_t)l * HD * HD, pWh, pWl, NW4);
        conv_split<<<1024, 256>>>(xin, pXh, pXl, NX4);
        gemm_tc<<<ggrid, 256>>>(pXh, pXl, pWh, pWl, bx + (size_t)l * HD, pA);
        rst_bar<<<1, 1>>>();
        float* xo = (l == NL - 1) ? out_x : pX;
        recur<<<NCTA, 256, SMEM_DYN>>>(pA, Wh + (size_t)l * HD * HD,
                                       lng + (size_t)l * HD, lnb + (size_t)l * HD, xo);
        xin = xo;
    }
    conv_split<<<512, 256>>>(Wy, pWh, pWl, NW4);
    conv_split<<<1024, 256>>>(out_x, pXh, pXl, NX4);
    gemm_tc<<<ggrid, 256>>>(pXh, pXl, pWh, pWl, by, out_y);
}

// round 8
// speedup vs baseline: 2.3187x; 1.0235x over previous
#include <cuda_runtime.h>
#include <cstdint>
#include <cstddef>

#define HD 1024
#define BA 64
#define TS 256
#define NL 4
#define MR (BA*TS)
#define NCTA 128
#define WP 34        // recur Ws pitch (floats)
#define GP 24        // gemm smem pitch (bf16 units)

// ---------------- device scratch ----------------
__device__ float    g_A[(size_t)MR * HD];
__device__ float    g_hT[HD * BA];          // h transposed: [k][b]
__device__ float2   g_st2[32 * BA];         // [ng][b] partial stats
__device__ unsigned g_bar4[4][32];          // bg-local barrier counters (128B apart)
__device__ uint16_t g_Xh[(size_t)MR * HD];  // x hi plane (bf16)
__device__ uint16_t g_Xl[(size_t)MR * HD];  // x lo plane
__device__ uint16_t g_Wph[(size_t)HD * HD]; // W hi plane
__device__ uint16_t g_Wpl[(size_t)HD * HD]; // W lo plane

typedef unsigned long long ull;

__device__ __forceinline__ void fma2(ull& d, ull a, ull b) {
    asm volatile("fma.rn.f32x2 %0, %1, %2, %0;" : "+l"(d) : "l"(a), "l"(b));
}
__device__ __forceinline__ void add2(ull& d, ull a) {
    asm volatile("add.rn.f32x2 %0, %0, %1;" : "+l"(d) : "l"(a));
}
__device__ __forceinline__ ull splat(float x) {
    ull d; asm("mov.b64 %0, {%1, %1};" : "=l"(d) : "f"(x)); return d;
}
__device__ __forceinline__ float2 unpk(ull v) {
    float2 r; asm("mov.b64 {%0, %1}, %2;" : "=f"(r.x), "=f"(r.y) : "l"(v)); return r;
}
__device__ __forceinline__ unsigned ldacq(const unsigned* p) {
    unsigned v; asm volatile("ld.acquire.gpu.u32 %0, [%1];" : "=r"(v) : "l"(p)); return v;
}
__device__ __forceinline__ void redrel(unsigned* p) {
    asm volatile("red.release.gpu.global.add.u32 [%0], 1;" :: "l"(p));
}
__device__ __forceinline__ void cpa16(void* dst, const void* src) {
    uint32_t d = (uint32_t)__cvta_generic_to_shared(dst);
    asm volatile("cp.async.cg.shared.global [%0], [%1], 16;" :: "r"(d), "l"(src));
}
__device__ __forceinline__ uint16_t bf16_bits(float x) {
    uint32_t u = __float_as_uint(x);
    return (uint16_t)((u + 0x7fffu + ((u >> 16) & 1u)) >> 16);
}
__device__ __forceinline__ float bf16f(uint16_t b) {
    return __uint_as_float(((uint32_t)b) << 16);
}
__device__ __forceinline__ void mma_bf16(float c[4], const uint32_t a[4], const uint32_t b[2]) {
    asm volatile(
        "mma.sync.aligned.m16n8k16.row.col.f32.bf16.bf16.f32 "
        "{%0,%1,%2,%3}, {%4,%5,%6,%7}, {%8,%9}, {%0,%1,%2,%3};"
        : "+f"(c[0]), "+f"(c[1]), "+f"(c[2]), "+f"(c[3])
        : "r"(a[0]), "r"(a[1]), "r"(a[2]), "r"(a[3]), "r"(b[0]), "r"(b[1]));
}

// =====================================================================
// fp32 -> (hi, lo) bf16 planes
// =====================================================================
__global__ void conv_split(const float* __restrict__ src,
                           uint16_t* __restrict__ hi, uint16_t* __restrict__ lo, int n4)
{
    for (int i = blockIdx.x * blockDim.x + threadIdx.x; i < n4; i += gridDim.x * blockDim.x) {
        float4 v = __ldcg((const float4*)src + i);
        uint16_t h0 = bf16_bits(v.x), h1 = bf16_bits(v.y);
        uint16_t h2 = bf16_bits(v.z), h3 = bf16_bits(v.w);
        uint16_t l0 = bf16_bits(v.x - bf16f(h0)), l1 = bf16_bits(v.y - bf16f(h1));
        uint16_t l2 = bf16_bits(v.z - bf16f(h2)), l3 = bf16_bits(v.w - bf16f(h3));
        ull hp = (ull)h0 | ((ull)h1 << 16) | ((ull)h2 << 32) | ((ull)h3 << 48);
        ull lp = (ull)l0 | ((ull)l1 << 16) | ((ull)l2 << 32) | ((ull)l3 << 48);
        ((ull*)hi)[i] = hp;
        ((ull*)lo)[i] = lp;
    }
}

// =====================================================================
// Tensor-core split-bf16 GEMM (validated R6): out = X @ W^T + bias
// =====================================================================
__global__ __launch_bounds__(256, 2) void gemm_tc(
    const uint16_t* __restrict__ Xh, const uint16_t* __restrict__ Xl,
    const uint16_t* __restrict__ Wh, const uint16_t* __restrict__ Wl,
    const float* __restrict__ bias, float* __restrict__ out)
{
    __shared__ uint16_t sm[2][4][128 * GP];

    const int tid = threadIdx.x;
    const int bn = blockIdx.x, bm = blockIdx.y;
    const int warp = tid >> 5, lane = tid & 31;
    const int g = lane >> 2, tq = lane & 3;
    const int wm = warp >> 1, wn = warp & 1;

    const uint16_t* gsrc[4];
    int pl[4], dof[4];
    #pragma unroll
    for (int j = 0; j < 4; j++) {
        int lin = j * 256 + tid;
        int plane = lin >> 8, rem = lin & 255;
        int row = rem >> 1, half = rem & 1;
        pl[j] = plane; dof[j] = row * GP + half * 8;
        const uint16_t* base;
        if      (plane == 0) base = Xh + (size_t)(bm * 128 + row) * HD;
        else if (plane == 1) base = Xl + (size_t)(bm * 128 + row) * HD;
        else if (plane == 2) base = Wh + (size_t)(bn * 128 + row) * HD;
        else                 base = Wl + (size_t)(bn * 128 + row) * HD;
        gsrc[j] = base + half * 8;
    }
    auto issue = [&](int buf, int c) {
        int k0 = c * 16;
        #pragma unroll
        for (int j = 0; j < 4; j++) cpa16(&sm[buf][pl[j]][dof[j]], gsrc[j] + k0);
        asm volatile("cp.async.commit_group;");
    };

    float acc[2][8][4];
    #pragma unroll
    for (int mt = 0; mt < 2; mt++)
        #pragma unroll
        for (int nt = 0; nt < 8; nt++)
            #pragma unroll
            for (int j = 0; j < 4; j++) acc[mt][nt][j] = 0.f;

    issue(0, 0);
    const int NCH = HD / 16;
    for (int c = 0; c < NCH; c++) {
        const int cur = c & 1;
        if (c + 1 < NCH) {
            issue(cur ^ 1, c + 1);
            asm volatile("cp.async.wait_group 1;");
        } else {
            asm volatile("cp.async.wait_group 0;");
        }
        __syncthreads();

        uint32_t aH[2][4], aL[2][4];
        #pragma unroll
        for (int mt = 0; mt < 2; mt++) {
            int row = wm * 32 + mt * 16 + g;
            aH[mt][0] = *(const uint32_t*)&sm[cur][0][row * GP + 2 * tq];
            aH[mt][1] = *(const uint32_t*)&sm[cur][0][(row + 8) * GP + 2 * tq];
            aH[mt][2] = *(const uint32_t*)&sm[cur][0][row * GP + 8 + 2 * tq];
            aH[mt][3] = *(const uint32_t*)&sm[cur][0][(row + 8) * GP + 8 + 2 * tq];
            aL[mt][0] = *(const uint32_t*)&sm[cur][1][row * GP + 2 * tq];
            aL[mt][1] = *(const uint32_t*)&sm[cur][1][(row + 8) * GP + 2 * tq];
            aL[mt][2] = *(const uint32_t*)&sm[cur][1][row * GP + 8 + 2 * tq];
            aL[mt][3] = *(const uint32_t*)&sm[cur][1][(row + 8) * GP + 8 + 2 * tq];
        }
        #pragma unroll
        for (int nt = 0; nt < 8; nt++) {
            int n = wn * 64 + nt * 8 + g;
            uint32_t bH[2], bL[2];
            bH[0] = *(const uint32_t*)&sm[cur][2][n * GP + 2 * tq];
            bH[1] = *(const uint32_t*)&sm[cur][2][n * GP + 8 + 2 * tq];
            bL[0] = *(const uint32_t*)&sm[cur][3][n * GP + 2 * tq];
            bL[1] = *(const uint32_t*)&sm[cur][3][n * GP + 8 + 2 * tq];
            #pragma unroll
            for (int mt = 0; mt < 2; mt++) {
                mma_bf16(acc[mt][nt], aH[mt], bH);
                mma_bf16(acc[mt][nt], aH[mt], bL);
                mma_bf16(acc[mt][nt], aL[mt], bH);
            }
        }
        __syncthreads();
    }

    #pragma unroll
    for (int mt = 0; mt < 2; mt++) {
        int row = bm * 128 + wm * 32 + mt * 16 + g;
        #pragma unroll
        for (int nt = 0; nt < 8; nt++) {
            int col = bn * 128 + wn * 64 + nt * 8 + 2 * tq;
            float b0 = __ldg(bias + col), b1 = __ldg(bias + col + 1);
            *(float2*)&out[(size_t)row * HD + col] =
                make_float2(acc[mt][nt][0] + b0, acc[mt][nt][1] + b1);
            *(float2*)&out[(size_t)(row + 8) * HD + col] =
                make_float2(acc[mt][nt][2] + b0, acc[mt][nt][3] + b1);
        }
    }
}

// =====================================================================
// Recurrence: bg-local barriers (4 groups x 32 CTAs), split-plane epilogue
// =====================================================================
__global__ void rst_bar4() { if (threadIdx.x < 4) g_bar4[threadIdx.x][0] = 0u; }

#define SMEM_DYN ((HD*WP + HD*16) * 4 + 8*16*17*8)

__global__ __launch_bounds__(256, 1) void recur(
    const float* __restrict__ A, const float* __restrict__ Wh,
    const float* __restrict__ lng, const float* __restrict__ lnb,
    uint16_t* __restrict__ xh, uint16_t* __restrict__ xl,
    float* __restrict__ xout)
{
    extern __shared__ char dsm[];
    float* Ws = (float*)dsm;                              // [1024][WP]
    float* Hs = (float*)(dsm + (size_t)HD*WP*4);          // [1024][16]
    ull*   red = (ull*)(dsm + (size_t)(HD*WP + HD*16)*4); // [8][16][17]
    __shared__ float s_mu[16], s_rs[16], s_g[32], s_b[32];

    const int tid = threadIdx.x, cta = blockIdx.x;
    const int bg = cta >> 5, ng = cta & 31;
    const int B0 = bg * 16, n0 = ng * 32;
    const int w = tid >> 5, lane = tid & 31;
    const int fh = lane & 15, bo = lane >> 4;
    const int b_i = tid >> 4, fp = tid & 15;

    for (int i = tid; i < 32 * HD; i += 256) {
        int k = i & 1023, f = i >> 10;
        Ws[k * WP + f] = Wh[(size_t)(n0 + f) * HD + k];
    }
    if (tid < 32) { s_g[tid] = lng[n0 + tid]; s_b[tid] = lnb[n0 + tid]; }
    if (tid < 128) {
        int rr = tid >> 2, q = tid & 3;
        __stcg((float4*)&g_hT[(n0 + rr) * BA + B0 + q * 4], make_float4(0.f,0.f,0.f,0.f));
    }
    __syncthreads();

    unsigned tgt = 0;
    unsigned* barp = &g_bar4[bg][0];
    auto gbar = [&]() {
        __syncthreads();
        tgt += 32;
        if (tid == 0) {
            redrel(barp);
            while (ldacq(barp) < tgt) { }
        }
        __syncthreads();
    };
    gbar();   // bg's h zero + prologue visible

    const int k0 = w * 128;
    float* HsW = Hs + k0 * 16;

    for (int t = 0; t < TS; t++) {
        float2 aA = __ldcg((const float2*)&A[((size_t)(B0 + b_i) * TS + t) * HD + n0 + fp * 2]);

        {
            const float* srcb = g_hT + (size_t)k0 * BA + B0;
            #pragma unroll
            for (int j = 0; j < 8; j++) {
                int lin = j * 32 + lane, kl = lin >> 2, q = lin & 3;
                cpa16(HsW + kl * 16 + q * 4, srcb + (size_t)kl * BA + q * 4);
            }
            asm volatile("cp.async.commit_group;");
            #pragma unroll
            for (int j = 8; j < 16; j++) {
                int lin = j * 32 + lane, kl = lin >> 2, q = lin & 3;
                cpa16(HsW + kl * 16 + q * 4, srcb + (size_t)kl * BA + q * 4);
            }
            asm volatile("cp.async.commit_group;");
        }

        ull acc[8];
        #pragma unroll
        for (int j = 0; j < 8; j++) acc[j] = 0ull;

        asm volatile("cp.async.wait_group 1;");
        #pragma unroll 8
        for (int k = k0; k < k0 + 64; k++) {
            ull w2 = *(const ull*)(Ws + (size_t)k * WP + fh * 2);
            float4 h0 = *(const float4*)(Hs + k * 16 + bo * 8);
            float4 h1 = *(const float4*)(Hs + k * 16 + bo * 8 + 4);
            fma2(acc[0], splat(h0.x), w2); fma2(acc[1], splat(h0.y), w2);
            fma2(acc[2], splat(h0.z), w2); fma2(acc[3], splat(h0.w), w2);
            fma2(acc[4], splat(h1.x), w2); fma2(acc[5], splat(h1.y), w2);
            fma2(acc[6], splat(h1.z), w2); fma2(acc[7], splat(h1.w), w2);
        }
        asm volatile("cp.async.wait_group 0;");
        #pragma unroll 8
        for (int k = k0 + 64; k < k0 + 128; k++) {
            ull w2 = *(const ull*)(Ws + (size_t)k * WP + fh * 2);
            float4 h0 = *(const float4*)(Hs + k * 16 + bo * 8);
            float4 h1 = *(const float4*)(Hs + k * 16 + bo * 8 + 4);
            fma2(acc[0], splat(h0.x), w2); fma2(acc[1], splat(h0.y), w2);
            fma2(acc[2], splat(h0.z), w2); fma2(acc[3], splat(h0.w), w2);
            fma2(acc[4], splat(h1.x), w2); fma2(acc[5], splat(h1.y), w2);
            fma2(acc[6], splat(h1.z), w2); fma2(acc[7], splat(h1.w), w2);
        }

        #pragma unroll
        for (int j = 0; j < 8; j++)
            red[(w * 16 + bo * 8 + j) * 17 + fh] = acc[j];
        __syncthreads();

        ull z = red[(0 * 16 + b_i) * 17 + fp];
        #pragma unroll
        for (int ww = 1; ww < 8; ww++) add2(z, red[(ww * 16 + b_i) * 17 + fp]);
        float2 z2 = unpk(z);
        z2.x += aA.x; z2.y += aA.y;

        float s = z2.x + z2.y;
        float q = z2.x * z2.x + z2.y * z2.y;
        s += __shfl_xor_sync(0xffffffffu, s, 1); q += __shfl_xor_sync(0xffffffffu, q, 1);
        s += __shfl_xor_sync(0xffffffffu, s, 2); q += __shfl_xor_sync(0xffffffffu, q, 2);
        s += __shfl_xor_sync(0xffffffffu, s, 4); q += __shfl_xor_sync(0xffffffffu, q, 4);
        s += __shfl_xor_sync(0xffffffffu, s, 8); q += __shfl_xor_sync(0xffffffffu, q, 8);
        if (fp == 0) __stcg((float2*)&g_st2[ng * BA + B0 + b_i], make_float2(s, q));
        gbar();   // bg-local: stats ready

        if (tid < 64) {
            int rr = tid >> 2, c = tid & 3;
            float ss = 0.f, qq = 0.f;
            #pragma unroll
            for (int m = 0; m < 8; m++) {
                float2 v = __ldcg((const float2*)&g_st2[(c * 8 + m) * BA + B0 + rr]);
                ss += v.x; qq += v.y;
            }
            ss += __shfl_xor_sync(0xffffffffu, ss, 1); qq += __shfl_xor_sync(0xffffffffu, qq, 1);
            ss += __shfl_xor_sync(0xffffffffu, ss, 2); qq += __shfl_xor_sync(0xffffffffu, qq, 2);
            if (c == 0) {
                float mu = ss * (1.f / HD);
                float var = qq * (1.f / HD) - mu * mu;
                s_mu[rr] = mu;
                s_rs[rr] = rsqrtf(var + 1e-5f);
            }
        }
        __syncthreads();

        const float mu = s_mu[b_i], rs = s_rs[b_i];
        const int f = fp * 2;
        float h0 = tanhf((z2.x - mu) * rs * s_g[f]     + s_b[f]);
        float h1 = tanhf((z2.y - mu) * rs * s_g[f + 1] + s_b[f + 1]);
        size_t xoff = ((size_t)(B0 + b_i) * TS + t) * HD + n0 + f;
        uint16_t hh0 = bf16_bits(h0), hh1 = bf16_bits(h1);
        uint16_t hl0 = bf16_bits(h0 - bf16f(hh0)), hl1 = bf16_bits(h1 - bf16f(hh1));
        *(uint32_t*)&xh[xoff] = (uint32_t)hh0 | ((uint32_t)hh1 << 16);
        *(uint32_t*)&xl[xoff] = (uint32_t)hl0 | ((uint32_t)hl1 << 16);
        if (xout) *(float2*)&xout[xoff] = make_float2(h0, h1);
        __stcg(&g_hT[(n0 + f) * BA + B0 + b_i], h0);
        __stcg(&g_hT[(n0 + f + 1) * BA + B0 + b_i], h1);
        gbar();   // bg-local: h ready
    }
}

// =====================================================================
extern "C" void kernel_launch(void* const* d_in, const int* in_sizes, int n_in,
                              void* d_out, int out_size)
{
    const float* inputs = (const float*)d_in[0];
    const float* Wx     = (const float*)d_in[1];
    const float* bx     = (const float*)d_in[2];
    const float* Wh     = (const float*)d_in[3];
    const float* lng    = (const float*)d_in[4];
    const float* lnb    = (const float*)d_in[5];
    const float* Wy     = (const float*)d_in[6];
    const float* by     = (const float*)d_in[7];

    float* out_x = (float*)d_out;
    float* out_y = out_x + (size_t)MR * HD;

    float* pA = nullptr;
    uint16_t *pXh, *pXl, *pWh, *pWl;
    cudaGetSymbolAddress((void**)&pA, g_A);
    cudaGetSymbolAddress((void**)&pXh, g_Xh);
    cudaGetSymbolAddress((void**)&pXl, g_Xl);
    cudaGetSymbolAddress((void**)&pWh, g_Wph);
    cudaGetSymbolAddress((void**)&pWl, g_Wpl);

    cudaFuncSetAttribute(recur, cudaFuncAttributeMaxDynamicSharedMemorySize, SMEM_DYN);

    dim3 ggrid(8, 128);
    const int NX4 = MR * HD / 4, NW4 = HD * HD / 4;

    // layer 0 input planes from harness input; later layers come from recur
    conv_split<<<1024, 256>>>(inputs, pXh, pXl, NX4);
    for (int l = 0; l < NL; l++) {
        conv_split<<<512, 256>>>(Wx + (size_t)l * HD * HD, pWh, pWl, NW4);
        gemm_tc<<<ggrid, 256>>>(pXh, pXl, pWh, pWl, bx + (size_t)l * HD, pA);
        rst_bar4<<<1, 32>>>();
        float* xo = (l == NL - 1) ? out_x : nullptr;
        recur<<<NCTA, 256, SMEM_DYN>>>(pA, Wh + (size_t)l * HD * HD,
                                       lng + (size_t)l * HD, lnb + (size_t)l * HD,
                                       pXh, pXl, xo);
    }
    conv_split<<<512, 256>>>(Wy, pWh, pWl, NW4);
    gemm_tc<<<ggrid, 256>>>(pXh, pXl, pWh, pWl, by, out_y);
}

// round 9
// speedup vs baseline: 2.5136x; 1.0841x over previous
#include <cuda_runtime.h>
#include <cstdint>
#include <cstddef>

#define HD 1024
#define BA 64
#define TS 256
#define NL 4
#define MR (BA*TS)
#define NCTA 128
#define GP 24        // gemm smem pitch (bf16 units)
#define RP 1032      // recur smem pitch (bf16 units) -> bank = 4*g + tq, conflict-free

// ---------------- device scratch ----------------
__device__ float    g_A[(size_t)MR * HD];
__device__ float2   g_st2[32 * BA];          // [ng][b] partial stats
__device__ unsigned g_bar4[4][32];           // bg-local barrier counters (128B apart)
__device__ uint16_t g_Xh[(size_t)MR * HD];   // x hi plane (bf16)
__device__ uint16_t g_Xl[(size_t)MR * HD];   // x lo plane
__device__ uint16_t g_Wph[(size_t)HD * HD];  // W hi plane
__device__ uint16_t g_Wpl[(size_t)HD * HD];  // W lo plane
__device__ uint16_t g_hbH[4 * 16 * HD];      // h hi plane per bg: [bg][16 rows][1024 f]
__device__ uint16_t g_hbL[4 * 16 * HD];      // h lo plane

typedef unsigned long long ull;

__device__ __forceinline__ unsigned ldacq(const unsigned* p) {
    unsigned v; asm volatile("ld.acquire.gpu.u32 %0, [%1];" : "=r"(v) : "l"(p)); return v;
}
__device__ __forceinline__ void redrel(unsigned* p) {
    asm volatile("red.release.gpu.global.add.u32 [%0], 1;" :: "l"(p));
}
__device__ __forceinline__ void cpa16(void* dst, const void* src) {
    uint32_t d = (uint32_t)__cvta_generic_to_shared(dst);
    asm volatile("cp.async.cg.shared.global [%0], [%1], 16;" :: "r"(d), "l"(src));
}
__device__ __forceinline__ uint16_t bf16_bits(float x) {
    uint32_t u = __float_as_uint(x);
    return (uint16_t)((u + 0x7fffu + ((u >> 16) & 1u)) >> 16);
}
__device__ __forceinline__ float bf16f(uint16_t b) {
    return __uint_as_float(((uint32_t)b) << 16);
}
__device__ __forceinline__ void mma_bf16(float c[4], const uint32_t a[4], const uint32_t b[2]) {
    asm volatile(
        "mma.sync.aligned.m16n8k16.row.col.f32.bf16.bf16.f32 "
        "{%0,%1,%2,%3}, {%4,%5,%6,%7}, {%8,%9}, {%0,%1,%2,%3};"
        : "+f"(c[0]), "+f"(c[1]), "+f"(c[2]), "+f"(c[3])
        : "r"(a[0]), "r"(a[1]), "r"(a[2]), "r"(a[3]), "r"(b[0]), "r"(b[1]));
}

// =====================================================================
// fp32 -> (hi, lo) bf16 planes
// =====================================================================
__global__ void conv_split(const float* __restrict__ src,
                           uint16_t* __restrict__ hi, uint16_t* __restrict__ lo, int n4)
{
    for (int i = blockIdx.x * blockDim.x + threadIdx.x; i < n4; i += gridDim.x * blockDim.x) {
        float4 v = __ldcg((const float4*)src + i);
        uint16_t h0 = bf16_bits(v.x), h1 = bf16_bits(v.y);
        uint16_t h2 = bf16_bits(v.z), h3 = bf16_bits(v.w);
        uint16_t l0 = bf16_bits(v.x - bf16f(h0)), l1 = bf16_bits(v.y - bf16f(h1));
        uint16_t l2 = bf16_bits(v.z - bf16f(h2)), l3 = bf16_bits(v.w - bf16f(h3));
        ull hp = (ull)h0 | ((ull)h1 << 16) | ((ull)h2 << 32) | ((ull)h3 << 48);
        ull lp = (ull)l0 | ((ull)l1 << 16) | ((ull)l2 << 32) | ((ull)l3 << 48);
        ((ull*)hi)[i] = hp;
        ((ull*)lo)[i] = lp;
    }
}

// =====================================================================
// Tensor-core split-bf16 GEMM (validated R6): out = X @ W^T + bias
// =====================================================================
__global__ __launch_bounds__(256, 2) void gemm_tc(
    const uint16_t* __restrict__ Xh, const uint16_t* __restrict__ Xl,
    const uint16_t* __restrict__ Wh, const uint16_t* __restrict__ Wl,
    const float* __restrict__ bias, float* __restrict__ out)
{
    __shared__ uint16_t sm[2][4][128 * GP];

    const int tid = threadIdx.x;
    const int bn = blockIdx.x, bm = blockIdx.y;
    const int warp = tid >> 5, lane = tid & 31;
    const int g = lane >> 2, tq = lane & 3;
    const int wm = warp >> 1, wn = warp & 1;

    const uint16_t* gsrc[4];
    int pl[4], dof[4];
    #pragma unroll
    for (int j = 0; j < 4; j++) {
        int lin = j * 256 + tid;
        int plane = lin >> 8, rem = lin & 255;
        int row = rem >> 1, half = rem & 1;
        pl[j] = plane; dof[j] = row * GP + half * 8;
        const uint16_t* base;
        if      (plane == 0) base = Xh + (size_t)(bm * 128 + row) * HD;
        else if (plane == 1) base = Xl + (size_t)(bm * 128 + row) * HD;
        else if (plane == 2) base = Wh + (size_t)(bn * 128 + row) * HD;
        else                 base = Wl + (size_t)(bn * 128 + row) * HD;
        gsrc[j] = base + half * 8;
    }
    auto issue = [&](int buf, int c) {
        int k0 = c * 16;
        #pragma unroll
        for (int j = 0; j < 4; j++) cpa16(&sm[buf][pl[j]][dof[j]], gsrc[j] + k0);
        asm volatile("cp.async.commit_group;");
    };

    float acc[2][8][4];
    #pragma unroll
    for (int mt = 0; mt < 2; mt++)
        #pragma unroll
        for (int nt = 0; nt < 8; nt++)
            #pragma unroll
            for (int j = 0; j < 4; j++) acc[mt][nt][j] = 0.f;

    issue(0, 0);
    const int NCH = HD / 16;
    for (int c = 0; c < NCH; c++) {
        const int cur = c & 1;
        if (c + 1 < NCH) {
            issue(cur ^ 1, c + 1);
            asm volatile("cp.async.wait_group 1;");
        } else {
            asm volatile("cp.async.wait_group 0;");
        }
        __syncthreads();

        uint32_t aH[2][4], aL[2][4];
        #pragma unroll
        for (int mt = 0; mt < 2; mt++) {
            int row = wm * 32 + mt * 16 + g;
            aH[mt][0] = *(const uint32_t*)&sm[cur][0][row * GP + 2 * tq];
            aH[mt][1] = *(const uint32_t*)&sm[cur][0][(row + 8) * GP + 2 * tq];
            aH[mt][2] = *(const uint32_t*)&sm[cur][0][row * GP + 8 + 2 * tq];
            aH[mt][3] = *(const uint32_t*)&sm[cur][0][(row + 8) * GP + 8 + 2 * tq];
            aL[mt][0] = *(const uint32_t*)&sm[cur][1][row * GP + 2 * tq];
            aL[mt][1] = *(const uint32_t*)&sm[cur][1][(row + 8) * GP + 2 * tq];
            aL[mt][2] = *(const uint32_t*)&sm[cur][1][row * GP + 8 + 2 * tq];
            aL[mt][3] = *(const uint32_t*)&sm[cur][1][(row + 8) * GP + 8 + 2 * tq];
        }
        #pragma unroll
        for (int nt = 0; nt < 8; nt++) {
            int n = wn * 64 + nt * 8 + g;
            uint32_t bH[2], bL[2];
            bH[0] = *(const uint32_t*)&sm[cur][2][n * GP + 2 * tq];
            bH[1] = *(const uint32_t*)&sm[cur][2][n * GP + 8 + 2 * tq];
            bL[0] = *(const uint32_t*)&sm[cur][3][n * GP + 2 * tq];
            bL[1] = *(const uint32_t*)&sm[cur][3][n * GP + 8 + 2 * tq];
            #pragma unroll
            for (int mt = 0; mt < 2; mt++) {
                mma_bf16(acc[mt][nt], aH[mt], bH);
                mma_bf16(acc[mt][nt], aH[mt], bL);
                mma_bf16(acc[mt][nt], aL[mt], bH);
            }
        }
        __syncthreads();
    }

    #pragma unroll
    for (int mt = 0; mt < 2; mt++) {
        int row = bm * 128 + wm * 32 + mt * 16 + g;
        #pragma unroll
        for (int nt = 0; nt < 8; nt++) {
            int col = bn * 128 + wn * 64 + nt * 8 + 2 * tq;
            float b0 = __ldg(bias + col), b1 = __ldg(bias + col + 1);
            *(float2*)&out[(size_t)row * HD + col] =
                make_float2(acc[mt][nt][0] + b0, acc[mt][nt][1] + b1);
            *(float2*)&out[(size_t)(row + 8) * HD + col] =
                make_float2(acc[mt][nt][2] + b0, acc[mt][nt][3] + b1);
        }
    }
}

// =====================================================================
// Recurrence v2: split-bf16 mma. 128 CTAs = 4 bg x 32 ng.
// CTA: 16 batch rows (M) x 32 features (N), K=1024.
// 8 warps = 4 n-tiles x 2 K-halves. h passed as bf16 hi/lo planes.
// =====================================================================
__global__ void rst_bar4() { if (threadIdx.x < 4) g_bar4[threadIdx.x][0] = 0u; }

#define RSMEM ((2*32*RP + 2*16*RP) * 2)   // 198144 B

__global__ __launch_bounds__(256, 1) void recur(
    const float* __restrict__ A, const float* __restrict__ Wh,
    const float* __restrict__ lng, const float* __restrict__ lnb,
    uint16_t* __restrict__ xh, uint16_t* __restrict__ xl,
    float* __restrict__ xout)
{
    extern __shared__ char dsm[];
    uint16_t* WsH = (uint16_t*)dsm;          // [32][RP]
    uint16_t* WsL = WsH + 32 * RP;
    uint16_t* HsH = WsL + 32 * RP;           // [16][RP]
    uint16_t* HsL = HsH + 16 * RP;
    __shared__ float4 red4[4][32];
    __shared__ float2 sst[4][16];
    __shared__ float s_mu[16], s_rs[16], s_g[32], s_b[32];

    const int tid = threadIdx.x, cta = blockIdx.x;
    const int bg = cta >> 5, ng = cta & 31;
    const int B0 = bg * 16, n0 = ng * 32;
    const int warp = tid >> 5, lane = tid & 31;
    const int nt = warp & 3, kh = warp >> 2;
    const int g = lane >> 2, tq = lane & 3;

    // ---- prologue: Ws planes [f][k], gamma/beta, zero our h-plane slice ----
    for (int idx = tid; idx < 32 * 512; idx += 256) {
        int f = idx >> 9, k = (idx & 511) * 2;
        float2 v = *(const float2*)&Wh[(size_t)(n0 + f) * HD + k];
        uint16_t h0 = bf16_bits(v.x), h1 = bf16_bits(v.y);
        uint16_t l0 = bf16_bits(v.x - bf16f(h0)), l1 = bf16_bits(v.y - bf16f(h1));
        *(uint32_t*)&WsH[f * RP + k] = (uint32_t)h0 | ((uint32_t)h1 << 16);
        *(uint32_t*)&WsL[f * RP + k] = (uint32_t)l0 | ((uint32_t)l1 << 16);
    }
    if (tid < 32) { s_g[tid] = lng[n0 + tid]; s_b[tid] = lnb[n0 + tid]; }
    {
        int row = tid >> 4, cp = tid & 15;               // 16 rows x 16 col-pairs = our 32 cols
        int off = bg * 16 * HD + row * HD + n0 + cp * 2;
        *(uint32_t*)&g_hbH[off] = 0u;
        *(uint32_t*)&g_hbL[off] = 0u;
    }
    __syncthreads();

    unsigned tgt = 0;
    unsigned* barp = &g_bar4[bg][0];
    auto gbar = [&]() {
        __syncthreads();
        tgt += 32;
        if (tid == 0) {
            __threadfence();
            redrel(barp);
            while (ldacq(barp) < tgt) { }
        }
        __syncthreads();
    };
    gbar();   // bg prologue visible

    const int f0 = n0 + nt * 8 + 2 * tq;   // this lane's feature pair (kh==0 epilogue)

    for (int t = 0; t < TS; t++) {
        // A prefetch for the two C-fragment rows (kh==0 warps only)
        float2 aAg, aAg8;
        if (kh == 0) {
            aAg  = __ldcg((const float2*)&A[((size_t)(B0 + g)     * TS + t) * HD + f0]);
            aAg8 = __ldcg((const float2*)&A[((size_t)(B0 + g + 8) * TS + t) * HD + f0]);
        }

        // fill Hs planes [16][1024] via cp.async (64 KB total)
        #pragma unroll
        for (int j = 0; j < 16; j++) {
            int lin = j * 256 + tid;
            int pl = lin >> 11, rem = lin & 2047;
            int row = rem >> 7, c = rem & 127;
            const uint16_t* src = (pl ? g_hbL : g_hbH) + bg * 16 * HD + row * HD + c * 8;
            uint16_t* dst = (pl ? HsL : HsH) + row * RP + c * 8;
            cpa16(dst, src);
        }
        asm volatile("cp.async.commit_group;");
        asm volatile("cp.async.wait_group 0;");
        __syncthreads();

        // mma over this warp's K-half
        float acc[4] = {0.f, 0.f, 0.f, 0.f};
        const int kb = kh * 512;
        const int nr = nt * 8 + g;
        #pragma unroll 4
        for (int ks = 0; ks < 32; ks++) {
            int kk = kb + ks * 16 + 2 * tq;
            uint32_t aH[4], aL[4], bH[2], bL[2];
            aH[0] = *(const uint32_t*)&HsH[g * RP + kk];
            aH[1] = *(const uint32_t*)&HsH[(g + 8) * RP + kk];
            aH[2] = *(const uint32_t*)&HsH[g * RP + kk + 8];
            aH[3] = *(const uint32_t*)&HsH[(g + 8) * RP + kk + 8];
            aL[0] = *(const uint32_t*)&HsL[g * RP + kk];
            aL[1] = *(const uint32_t*)&HsL[(g + 8) * RP + kk];
            aL[2] = *(const uint32_t*)&HsL[g * RP + kk + 8];
            aL[3] = *(const uint32_t*)&HsL[(g + 8) * RP + kk + 8];
            bH[0] = *(const uint32_t*)&WsH[nr * RP + kk];
            bH[1] = *(const uint32_t*)&WsH[nr * RP + kk + 8];
            bL[0] = *(const uint32_t*)&WsL[nr * RP + kk];
            bL[1] = *(const uint32_t*)&WsL[nr * RP + kk + 8];
            mma_bf16(acc, aH, bH);
            mma_bf16(acc, aH, bL);
            mma_bf16(acc, aL, bH);
        }

        // 2-way K reduce: kh==1 stores, kh==0 adds
        if (kh == 1) red4[nt][lane] = make_float4(acc[0], acc[1], acc[2], acc[3]);
        __syncthreads();

        if (kh == 0) {
            float4 o = red4[nt][lane];
            acc[0] += o.x + aAg.x;  acc[1] += o.y + aAg.y;
            acc[2] += o.z + aAg8.x; acc[3] += o.w + aAg8.y;

            // partial LN stats: rows g and g+8, this warp's 8 features
            float sA = acc[0] + acc[1], qA = acc[0]*acc[0] + acc[1]*acc[1];
            float sB = acc[2] + acc[3], qB = acc[2]*acc[2] + acc[3]*acc[3];
            sA += __shfl_xor_sync(0xffffffffu, sA, 1); qA += __shfl_xor_sync(0xffffffffu, qA, 1);
            sA += __shfl_xor_sync(0xffffffffu, sA, 2); qA += __shfl_xor_sync(0xffffffffu, qA, 2);
            sB += __shfl_xor_sync(0xffffffffu, sB, 1); qB += __shfl_xor_sync(0xffffffffu, qB, 1);
            sB += __shfl_xor_sync(0xffffffffu, sB, 2); qB += __shfl_xor_sync(0xffffffffu, qB, 2);
            if (tq == 0) {
                sst[nt][g]     = make_float2(sA, qA);
                sst[nt][g + 8] = make_float2(sB, qB);
            }
        }
        __syncthreads();
        if (tid < 16) {
            float2 v0 = sst[0][tid], v1 = sst[1][tid], v2 = sst[2][tid], v3 = sst[3][tid];
            float2 o = make_float2(v0.x + v1.x + v2.x + v3.x, v0.y + v1.y + v2.y + v3.y);
            *(float2*)&g_st2[ng * BA + B0 + tid] = o;
        }
        gbar();   // bg-local: stats ready

        if (tid < 64) {
            int rr = tid >> 2, c = tid & 3;
            float ss = 0.f, qq = 0.f;
            #pragma unroll
            for (int m = 0; m < 8; m++) {
                float2 v = __ldcg((const float2*)&g_st2[(c * 8 + m) * BA + B0 + rr]);
                ss += v.x; qq += v.y;
            }
            ss += __shfl_xor_sync(0xffffffffu, ss, 1); qq += __shfl_xor_sync(0xffffffffu, qq, 1);
            ss += __shfl_xor_sync(0xffffffffu, ss, 2); qq += __shfl_xor_sync(0xffffffffu, qq, 2);
            if (c == 0) {
                float mu = ss * (1.f / HD);
                float var = qq * (1.f / HD) - mu * mu;
                s_mu[rr] = mu;
                s_rs[rr] = rsqrtf(var + 1e-5f);
            }
        }
        __syncthreads();

        if (kh == 0) {
            float muA = s_mu[g],     rsA = s_rs[g];
            float muB = s_mu[g + 8], rsB = s_rs[g + 8];
            int fl = nt * 8 + 2 * tq;
            float ga0 = s_g[fl], be0 = s_b[fl], ga1 = s_g[fl + 1], be1 = s_b[fl + 1];
            float h0 = tanhf((acc[0] - muA) * rsA * ga0 + be0);
            float h1 = tanhf((acc[1] - muA) * rsA * ga1 + be1);
            float h2 = tanhf((acc[2] - muB) * rsB * ga0 + be0);
            float h3 = tanhf((acc[3] - muB) * rsB * ga1 + be1);

            uint16_t a0 = bf16_bits(h0), a1 = bf16_bits(h1);
            uint16_t c0 = bf16_bits(h2), c1 = bf16_bits(h3);
            uint32_t hiA = (uint32_t)a0 | ((uint32_t)a1 << 16);
            uint32_t hiB = (uint32_t)c0 | ((uint32_t)c1 << 16);
            uint32_t loA = (uint32_t)bf16_bits(h0 - bf16f(a0)) |
                           ((uint32_t)bf16_bits(h1 - bf16f(a1)) << 16);
            uint32_t loB = (uint32_t)bf16_bits(h2 - bf16f(c0)) |
                           ((uint32_t)bf16_bits(h3 - bf16f(c1)) << 16);

            size_t xoA = ((size_t)(B0 + g)     * TS + t) * HD + f0;
            size_t xoB = ((size_t)(B0 + g + 8) * TS + t) * HD + f0;
            *(uint32_t*)&xh[xoA] = hiA; *(uint32_t*)&xl[xoA] = loA;
            *(uint32_t*)&xh[xoB] = hiB; *(uint32_t*)&xl[xoB] = loB;

            int hoA = bg * 16 * HD + g * HD + f0;
            int hoB = bg * 16 * HD + (g + 8) * HD + f0;
            *(uint32_t*)&g_hbH[hoA] = hiA; *(uint32_t*)&g_hbL[hoA] = loA;
            *(uint32_t*)&g_hbH[hoB] = hiB; *(uint32_t*)&g_hbL[hoB] = loB;

            if (xout) {
                *(float2*)&xout[xoA] = make_float2(h0, h1);
                *(float2*)&xout[xoB] = make_float2(h2, h3);
            }
        }
        gbar();   // bg-local: h ready
    }
}

// =====================================================================
extern "C" void kernel_launch(void* const* d_in, const int* in_sizes, int n_in,
                              void* d_out, int out_size)
{
    const float* inputs = (const float*)d_in[0];
    const float* Wx     = (const float*)d_in[1];
    const float* bx     = (const float*)d_in[2];
    const float* Wh     = (const float*)d_in[3];
    const float* lng    = (const float*)d_in[4];
    const float* lnb    = (const float*)d_in[5];
    const float* Wy     = (const float*)d_in[6];
    const float* by     = (const float*)d_in[7];

    float* out_x = (float*)d_out;
    float* out_y = out_x + (size_t)MR * HD;

    float* pA = nullptr;
    uint16_t *pXh, *pXl, *pWh, *pWl;
    cudaGetSymbolAddress((void**)&pA, g_A);
    cudaGetSymbolAddress((void**)&pXh, g_Xh);
    cudaGetSymbolAddress((void**)&pXl, g_Xl);
    cudaGetSymbolAddress((void**)&pWh, g_Wph);
    cudaGetSymbolAddress((void**)&pWl, g_Wpl);

    cudaFuncSetAttribute(recur, cudaFuncAttributeMaxDynamicSharedMemorySize, RSMEM);

    dim3 ggrid(8, 128);
    const int NX4 = MR * HD / 4, NW4 = HD * HD / 4;

    conv_split<<<1024, 256>>>(inputs, pXh, pXl, NX4);
    for (int l = 0; l < NL; l++) {
        conv_split<<<512, 256>>>(Wx + (size_t)l * HD * HD, pWh, pWl, NW4);
        gemm_tc<<<ggrid, 256>>>(pXh, pXl, pWh, pWl, bx + (size_t)l * HD, pA);
        rst_bar4<<<1, 32>>>();
        float* xo = (l == NL - 1) ? out_x : nullptr;
        recur<<<NCTA, 256, RSMEM>>>(pA, Wh + (size_t)l * HD * HD,
                                    lng + (size_t)l * HD, lnb + (size_t)l * HD,
                                    pXh, pXl, xo);
    }
    conv_split<<<512, 256>>>(Wy, pWh, pWl, NW4);
    gemm_tc<<<ggrid, 256>>>(pXh, pXl, pWh, pWl, by, out_y);
}